// round 5
// baseline (speedup 1.0000x reference)
#include <cuda_runtime.h>
#include <cstddef>

// Problem constants (fixed by the dataset instance)
#define MM   4
#define AA   256
#define RBF  64
#define FF   32
#define HH   32
#define SI   32
#define CC   128   // 4 filters * FF radial columns

// Precombined radial weights: W[c][k] (column-major in k, 64 floats per column)
__device__ float g_W[CC * RBF];
__device__ float g_bias[CC];

struct Wptrs {
    const float* w1[4];
    const float* b1[4];
    const float* w2[4];
    const float* b2[4];
};

// ---------------------------------------------------------------------------
// Precompute W = w1 @ w2 (per filter), bias = b1 @ w2 + b2.
// Stored as g_W[c*64 + k], c = filt*32 + f  (filt order: 00, 01, 10, 11).
// ---------------------------------------------------------------------------
__global__ void prep_kernel(Wptrs wp) {
    int idx = blockIdx.x * blockDim.x + threadIdx.x;
    if (idx < CC * RBF) {
        int c = idx >> 6;        // 0..127
        int k = idx & 63;        // 0..63
        int filt = c >> 5;
        int f = c & 31;
        const float* w1 = wp.w1[filt];
        const float* w2 = wp.w2[filt];
        float s = 0.f;
#pragma unroll
        for (int h = 0; h < HH; h++)
            s += w1[k * HH + h] * w2[h * FF + f];
        g_W[c * RBF + k] = s;
        if (k == 0) {
            float bs = wp.b2[filt][f];
            const float* b1 = wp.b1[filt];
#pragma unroll
            for (int h = 0; h < HH; h++)
                bs += b1[h] * w2[h * FF + f];
            g_bias[c] = bs;
        }
    }
}

// ---------------------------------------------------------------------------
// Packed fp32x2 FMA (Blackwell FFMA2 — PTX-only path, 2 FMAs / instruction)
// ---------------------------------------------------------------------------
typedef unsigned long long u64;

__device__ __forceinline__ u64 ffma2(u64 a, u64 b, u64 c) {
    u64 d;
    asm("fma.rn.f32x2 %0, %1, %2, %3;" : "=l"(d) : "l"(a), "l"(b), "l"(c));
    return d;
}

__device__ __forceinline__ float hsum2(u64 a) {
    float lo, hi;
    asm("mov.b64 {%0, %1}, %2;" : "=f"(lo), "=f"(hi) : "l"(a));
    return lo + hi;
}

__device__ __forceinline__ float sspf(float x) {
    // shifted softplus: log(0.5*exp(x) + 0.5)
    return logf(0.5f * expf(x) + 0.5f);
}

// ---------------------------------------------------------------------------
// Main fused kernel: one block per (m, a).
// 256 threads = 64 column-threads (cc) x 4 b-groups (bg).
//   cc <  32 (type A): columns cc      (filter 00) and cc+64 (filter 10)
//   cc >= 32 (type B): columns cc      (filter 01) and cc+64 (filter 11)
// Each thread keeps its 2 columns' W (64 u64 = 128 regs) in registers and
// streams the image row through double-buffered shared memory.
// ---------------------------------------------------------------------------
__global__ void __launch_bounds__(256, 1) conv_kernel(
    const float* __restrict__ image,
    const float* __restrict__ vectors,
    const float* __restrict__ feat0,
    const float* __restrict__ feat1,
    const float* __restrict__ w_si0,
    const float* __restrict__ w_si1,
    const float* __restrict__ b_act0,
    const float* __restrict__ b_act1,
    float* __restrict__ out)
{
    const int ma  = blockIdx.x;        // m*AA + a
    const int m   = ma >> 8;           // AA = 256
    const int tid = threadIdx.x;
    const int cc  = tid & 63;
    const int bg  = tid >> 6;          // 0..3
    const int f   = cc & 31;
    const bool typeA = (cc < 32);

    __shared__ float s_img[2][8][RBF];   // double-buffered tile of 8 image rows
    __shared__ float s_v[2][8][4];       // vectors for the 8 rows (padded)
    __shared__ float s_red[4][64][8];    // cross-b-group reduction
    __shared__ float s_cat[32][12];      // reduced cat features per f (padded)

    // --- Load this thread's two weight columns into registers ---
    const int c0 = cc;
    const int c1 = cc + 64;
    u64 W0[32], W1[32];
    {
        const u64* wp0 = (const u64*)(g_W + c0 * RBF);
        const u64* wp1 = (const u64*)(g_W + c1 * RBF);
#pragma unroll
        for (int i = 0; i < 32; i++) { W0[i] = wp0[i]; W1[i] = wp1[i]; }
    }
    const float bias0 = g_bias[c0];
    const float bias1 = g_bias[c1];

    const float* imgbase = image   + (size_t)ma * (AA * RBF);
    const float* vbase   = vectors + (size_t)ma * (AA * 3);
    const float* f0base  = feat0   + (size_t)m  * (AA * FF);
    const float* f1base  = feat1   + (size_t)m  * (AA * FF * 3);

    float acc[7];
#pragma unroll
    for (int j = 0; j < 7; j++) acc[j] = 0.f;

    // staging helper: copy 8 image rows (512 floats) + 8 vectors (24 floats)
    auto stage = [&](int bf, int bt) {
        if (tid < 128) {
            ((float4*)&s_img[bf][0][0])[tid] =
                ((const float4*)(imgbase + (size_t)bt * RBF))[tid];
        } else if (tid < 152) {
            int u = tid - 128;
            s_v[bf][u / 3][u % 3] = vbase[bt * 3 + u];
        }
    };

    stage(0, 0);
    int buf = 0;

    for (int t = 0; t < 32; t++) {
        __syncthreads();
        if (t + 1 < 32) stage(buf ^ 1, (t + 1) * 8);

        // compute current tile from s_img[buf]
#pragma unroll
        for (int s2 = 0; s2 < 2; s2++) {
            const int j = bg * 2 + s2;
            const int b = t * 8 + j;

            u64 a0 = 0ULL, a1 = 0ULL;
            const u64* ip = (const u64*)(&s_img[buf][j][0]);
#pragma unroll
            for (int k2 = 0; k2 < 32; k2++) {
                u64 iv = ip[k2];
                a0 = ffma2(iv, W0[k2], a0);
                a1 = ffma2(iv, W1[k2], a1);
            }
            float r0 = hsum2(a0) + bias0;
            float r1 = hsum2(a1) + bias1;

            const float p0 = f0base[b * FF + f];
            const float* q = f1base + (size_t)(b * FF + f) * 3;
            const float q0 = q[0], q1 = q[1], q2 = q[2];

            if (typeA) {
                // filter 00: out_0x0_0 ; filter 10: out_1x0_1
                acc[0] = fmaf(r0, p0, acc[0]);
                acc[1] = fmaf(r1, q0, acc[1]);
                acc[2] = fmaf(r1, q1, acc[2]);
                acc[3] = fmaf(r1, q2, acc[3]);
            } else {
                // filter 01: out_0x1_1 ; filter 11: out_1x1_0 & out_1x1_1
                const float vx = s_v[buf][j][0];
                const float vy = s_v[buf][j][1];
                const float vz = s_v[buf][j][2];
                const float n2 = vx * vx + vy * vy + vz * vz;
                if (n2 < 1e-14f) { r0 = 0.f; r1 = 0.f; }  // |v| < 1e-7 mask
                const float tp = r0 * p0;
                acc[0] = fmaf(tp, vx, acc[0]);
                acc[1] = fmaf(tp, vy, acc[1]);
                acc[2] = fmaf(tp, vz, acc[2]);
                acc[3] = fmaf(r1, vx * q0 + vy * q1 + vz * q2, acc[3]); // v.q
                acc[4] = fmaf(r1, vy * q2 - vz * q1, acc[4]);           // (v x q)x
                acc[5] = fmaf(r1, vz * q0 - vx * q2, acc[5]);           // (v x q)y
                acc[6] = fmaf(r1, vx * q1 - vy * q0, acc[6]);           // (v x q)z
            }
        }
        buf ^= 1;
    }

    // --- reduce across the 4 b-groups ---
#pragma unroll
    for (int j = 0; j < 7; j++) s_red[bg][cc][j] = acc[j];
    __syncthreads();

    if (tid < 64) {
        float s[7];
#pragma unroll
        for (int j = 0; j < 7; j++)
            s[j] = s_red[0][tid][j] + s_red[1][tid][j] +
                   s_red[2][tid][j] + s_red[3][tid][j];
        if (tid < 32) {
            // type A: a00 -> slot 0 ; a10(xyz) -> 4..6
            s_cat[tid][0] = s[0];
            s_cat[tid][4] = s[1];
            s_cat[tid][5] = s[2];
            s_cat[tid][6] = s[3];
        } else {
            // type B: a01(xyz) -> 1..3 ; a110 -> 7 ; a111(xyz) -> 8..10
            int ff = tid - 32;
            s_cat[ff][1] = s[0];
            s_cat[ff][2] = s[1];
            s_cat[ff][3] = s[2];
            s_cat[ff][7] = s[3];
            s_cat[ff][8] = s[4];
            s_cat[ff][9] = s[5];
            s_cat[ff][10] = s[6];
        }
    }
    __syncthreads();

    // --- self-interaction + equivariant activation ---
    if (tid < 32) {
        const int g = tid;
        const float* w0p = w_si0 + g * (2 * FF);
        const float* w1p = w_si1 + g * (3 * FF);
        float si0 = 0.f, sx = 0.f, sy = 0.f, sz = 0.f;
#pragma unroll 8
        for (int f2 = 0; f2 < 32; f2++) {
            const float* c = s_cat[f2];
            si0 += w0p[f2] * c[0] + w0p[32 + f2] * c[7];
            const float wa = w1p[f2], wb = w1p[32 + f2], wc = w1p[64 + f2];
            sx += wa * c[1] + wb * c[4] + wc * c[8];
            sy += wa * c[2] + wb * c[5] + wc * c[9];
            sz += wa * c[3] + wb * c[6] + wc * c[10];
        }
        const float o0v = sspf(si0 + b_act0[g]);
        const float nn  = sx * sx + sy * sy + sz * sz;
        const float n1  = sqrtf(fmaxf(nn, 1e-7f));
        const float a1v = sspf(n1 + b_act1[g]);
        const float sc  = a1v / n1;

        out[(size_t)ma * SI + g] = o0v;                      // o0: (M,A,SI,1)
        float* o1 = out + (size_t)MM * AA * SI + ((size_t)ma * SI + g) * 3;
        o1[0] = sx * sc;
        o1[1] = sy * sc;
        o1[2] = sz * sc;
    }
}

// ---------------------------------------------------------------------------
extern "C" void kernel_launch(void* const* d_in, const int* in_sizes, int n_in,
                              void* d_out, int out_size)
{
    (void)in_sizes; (void)n_in; (void)out_size;

    const float* image   = (const float*)d_in[0];
    const float* vectors = (const float*)d_in[1];
    const float* feat0   = (const float*)d_in[2];
    const float* feat1   = (const float*)d_in[3];

    Wptrs wp;
    for (int filt = 0; filt < 4; filt++) {
        wp.w1[filt] = (const float*)d_in[4 + filt * 4 + 0];
        wp.b1[filt] = (const float*)d_in[4 + filt * 4 + 1];
        wp.w2[filt] = (const float*)d_in[4 + filt * 4 + 2];
        wp.b2[filt] = (const float*)d_in[4 + filt * 4 + 3];
    }
    const float* w_si0  = (const float*)d_in[20];
    const float* w_si1  = (const float*)d_in[21];
    const float* b_act0 = (const float*)d_in[22];
    const float* b_act1 = (const float*)d_in[23];

    prep_kernel<<<32, 256>>>(wp);
    conv_kernel<<<MM * AA, 256>>>(image, vectors, feat0, feat1,
                                  w_si0, w_si1, b_act0, b_act1,
                                  (float*)d_out);
}